// round 3
// baseline (speedup 1.0000x reference)
#include <cuda_runtime.h>
#include <cstdint>

#define Hh 128
#define Ww 128
#define HW (128*128)
#define Bb 8
#define Gg 2
#define GC 32
#define SC 288
#define GF 64

// ---------------- scratch (allocation-free: __device__ globals) ----------------
__device__ float g_off[(size_t)Bb*Gg*HW*18];          // offsets, [bg][p][k][2]
__device__ float g_samp[(size_t)Bb*Gg*HW*SC];         // samples, [bg][p][k*32+c]

// ---------------- f32x2 packed helpers ----------------
__device__ __forceinline__ unsigned long long pack2(float a, float b) {
    unsigned long long d;
    asm("mov.b64 %0, {%1, %2};" : "=l"(d) : "f"(a), "f"(b));
    return d;
}
__device__ __forceinline__ float2 unpack2(unsigned long long v) {
    float2 r;
    asm("mov.b64 {%0, %1}, %2;" : "=f"(r.x), "=f"(r.y) : "l"(v));
    return r;
}
__device__ __forceinline__ unsigned long long fma2(unsigned long long a,
                                                   unsigned long long b,
                                                   unsigned long long c) {
    unsigned long long d;
    asm("fma.rn.f32x2 %0, %1, %2, %3;" : "=l"(d) : "l"(a), "l"(b), "l"(c));
    return d;
}

// =====================================================================
// Kernel A: offset conv (3x3, 32 -> 18 ch, SAME, per group)
// grid (8, 4, B*G): tile 16 wide x 32 tall. 256 threads, 2 pixels/thread.
// smem: input tile (34 rows x 18 cols x 32 ch, ch-pad 33) + weights (9*32*18).
// Weights read via uniform-broadcast LDS (under the fma issue budget).
// =====================================================================
__global__ void __launch_bounds__(256) k_offconv(const float* __restrict__ x,
                                                 const float* __restrict__ ow,
                                                 const float* __restrict__ ob)
{
    extern __shared__ float s[];
    float* s_in = s;                         // 34*18*33 = 20196
    float* s_w  = s + 34 * 18 * 33;          // 9*32*18  = 5184

    const int bg = blockIdx.z;
    const int b = bg >> 1, g = bg & 1;
    const int tx0 = blockIdx.x * 16, ty0 = blockIdx.y * 32;
    const float* xb = x + (size_t)b * HW * 64 + g * 32;
    const float* wg = ow + (size_t)g * 9 * 32 * 18;

    for (int i = threadIdx.x; i < 9 * 32 * 18; i += 256) s_w[i] = wg[i];

    for (int i = threadIdx.x; i < 34 * 18 * 32; i += 256) {
        int c   = i & 31;
        int col = (i >> 5) % 18;
        int row = i / (32 * 18);
        int gy = ty0 - 1 + row, gx = tx0 - 1 + col;
        float v = 0.f;
        if ((unsigned)gy < Hh && (unsigned)gx < Ww)
            v = xb[(size_t)(gy * Ww + gx) * 64 + c];
        s_in[(row * 18 + col) * 33 + c] = v;
    }
    __syncthreads();

    const int tx = threadIdx.x & 15, ty = threadIdx.x >> 4;

    unsigned long long acc0[9], acc1[9];
    const float2* ob2 = (const float2*)(ob + g * 18);
#pragma unroll
    for (int j = 0; j < 9; j++) {
        float2 bb = ob2[j];
        acc0[j] = pack2(bb.x, bb.y);
        acc1[j] = acc0[j];
    }

#pragma unroll
    for (int ky = 0; ky < 3; ky++) {
#pragma unroll
        for (int kx = 0; kx < 3; kx++) {
            const float* wt = s_w + (size_t)((ky * 3 + kx) * 32) * 18;
            const int sb0 = ((ty + ky) * 18 + tx + kx) * 33;
            const int sb1 = ((ty + 16 + ky) * 18 + tx + kx) * 33;
#pragma unroll 4
            for (int c = 0; c < 32; c++) {
                float v0 = s_in[sb0 + c];
                float v1 = s_in[sb1 + c];
                unsigned long long p0 = pack2(v0, v0);
                unsigned long long p1 = pack2(v1, v1);
                const unsigned long long* wp =
                    (const unsigned long long*)(wt + c * 18);
#pragma unroll
                for (int j = 0; j < 9; j++) {
                    unsigned long long wj = wp[j];
                    acc0[j] = fma2(p0, wj, acc0[j]);
                    acc1[j] = fma2(p1, wj, acc1[j]);
                }
            }
        }
    }

    const int gx = tx0 + tx;
    unsigned long long* o0 = (unsigned long long*)(g_off +
        ((size_t)bg * HW + (ty0 + ty) * Ww + gx) * 18);
    unsigned long long* o1 = (unsigned long long*)(g_off +
        ((size_t)bg * HW + (ty0 + ty + 16) * Ww + gx) * 18);
#pragma unroll
    for (int j = 0; j < 9; j++) { o0[j] = acc0[j]; o1[j] = acc1[j]; }
}

// =====================================================================
// Kernel B: bilinear sampling.
// thread = (bg, p, k, c4) with c4 = channel quad (8 per tap).
// Exactly replicates the reference clip/floor/weight formula
// (including the zero-weight artifact at the high boundary).
// =====================================================================
__global__ void __launch_bounds__(256) k_sample(const float* __restrict__ x)
{
    const unsigned t = blockIdx.x * 256u + threadIdx.x;
    const int c4 = t & 7;
    const int k  = (t >> 3) % 9;
    const unsigned rest = t / 72u;
    const int p  = rest & (HW - 1);
    const int bg = rest >> 14;
    const int b = bg >> 1, g = bg & 1;

    const float2 off2 = ((const float2*)g_off)[((size_t)bg * HW + p) * 9 + k];
    const int px = p & 127, py = p >> 7;

    float lx = (float)px + (float)(k % 3 - 1) + off2.x;
    float ly = (float)py + (float)(k / 3 - 1) + off2.y;
    lx = fminf(fmaxf(lx, 0.f), 127.f);
    ly = fminf(fmaxf(ly, 0.f), 127.f);

    float fx = floorf(lx), fy = floorf(ly);
    float x0f = fminf(fmaxf(fx, 0.f), 127.f);
    float x1f = fminf(fmaxf(fx + 1.f, 0.f), 127.f);
    float y0f = fminf(fmaxf(fy, 0.f), 127.f);
    float y1f = fminf(fmaxf(fy + 1.f, 0.f), 127.f);

    float wa = (x1f - lx) * (y1f - ly);
    float wb = (x1f - lx) * (ly - y0f);
    float wc = (lx - x0f) * (y1f - ly);
    float wd = (lx - x0f) * (ly - y0f);

    int x0 = (int)x0f, x1 = (int)x1f, y0 = (int)y0f, y1 = (int)y1f;

    const float* xc = x + (size_t)b * HW * 64 + g * 32 + c4 * 4;
    const float4 Ia = *(const float4*)(xc + (size_t)(y0 * Ww + x0) * 64);
    const float4 Ib = *(const float4*)(xc + (size_t)(y1 * Ww + x0) * 64);
    const float4 Ic = *(const float4*)(xc + (size_t)(y0 * Ww + x1) * 64);
    const float4 Id = *(const float4*)(xc + (size_t)(y1 * Ww + x1) * 64);

    float4 r;
    r.x = wa * Ia.x + wb * Ib.x + wc * Ic.x + wd * Id.x;
    r.y = wa * Ia.y + wb * Ib.y + wc * Ic.y + wd * Id.y;
    r.z = wa * Ia.z + wb * Ib.z + wc * Ic.z + wd * Id.z;
    r.w = wa * Ia.w + wb * Ib.w + wc * Ic.w + wd * Id.w;

    *(float4*)(g_samp + ((size_t)bg * HW + p) * SC + k * 32 + c4 * 4) = r;
}

// =====================================================================
// Kernel C: fused depthwise 3x3 (groups=SC) + pointwise (SC -> 64).
// grid (8, 8, B*G): 16x16 pixel tile. 256 threads.
// 9 TAP-chunks of 32 channels:
//   stage: samp halo tile 18x18x32 -> smem (zero-padded = SAME padding),
//          pw weight slab 32x64 -> smem
//   phase1: depthwise from smem -> dsh transposed [ch][pix] (stride 260)
//   phase2: register-tiled GEMM: warp = 8 filters, lane = 8 pixels, f32x2.
// dw weights (9x288) staged once per block.
// =====================================================================
__global__ void __launch_bounds__(256) k_dwpw(const float* __restrict__ dww,
                                              const float* __restrict__ dwb,
                                              const float* __restrict__ pww,
                                              const float* __restrict__ pwb,
                                              float* __restrict__ out)
{
    extern __shared__ float sm[];
    float* sA  = sm;                          // 324*33  = 10692 (halo tile)
    float* dsh = sm + 10692;                  // 32*260  = 8320  (dw out, [ch][pix])
    float* sW  = sm + 10692 + 8320;           // 9*288   = 2592  (dw weights)
    float* sP  = sm + 10692 + 8320 + 2592;    // 32*64   = 2048  (pw weight slab)

    const int bg = blockIdx.z;
    const int b = bg >> 1, g = bg & 1;
    const int tx0 = blockIdx.x * 16, ty0 = blockIdx.y * 16;
    const float* sb = g_samp + (size_t)bg * HW * SC;
    const int tid = threadIdx.x;
    const int lane = tid & 31, fg = tid >> 5;

    // stage depthwise weights once: sW[(ky*3+kx)*288 + ch]
    for (int i = tid; i < 9 * SC; i += 256) sW[i] = dww[(size_t)g * 9 * SC + i];

    unsigned long long acc[8][4];
#pragma unroll
    for (int f = 0; f < 8; f++)
#pragma unroll
        for (int q = 0; q < 4; q++) acc[f][q] = 0ull;

    for (int k = 0; k < 9; k++) {
        const int c0 = k * 32;
        __syncthreads();   // prev GEMM done reading dsh/sP before restage

        // ----- stage samp halo tile (18x18 x 32ch) and pw slab -----
        for (int i = tid; i < 324 * 32; i += 256) {
            const int c   = i & 31;
            const int pos = i >> 5;
            const int col = pos % 18, row = pos / 18;
            const int gy = ty0 - 1 + row, gx = tx0 - 1 + col;
            float v = 0.f;
            if ((unsigned)gy < Hh && (unsigned)gx < Ww)
                v = sb[(size_t)(gy * Ww + gx) * SC + c0 + c];
            sA[pos * 33 + c] = v;
        }
        for (int i = tid; i < 32 * 64; i += 256)
            sP[i] = pww[((size_t)g * SC + c0) * 64 + i];
        __syncthreads();

        // ----- phase 1: depthwise into dsh, transposed [ch][pix] -----
        for (int it = tid; it < 64 * 32; it += 256) {
            const int ch = it & 31;          // warp = 32 consecutive ch
            const int p4 = it >> 5;          // 4 consecutive pixels
            const int px0 = (p4 & 3) * 4;
            const int py  = p4 >> 2;
            float a0 = 0.f, a1 = 0.f, a2 = 0.f, a3 = 0.f;
#pragma unroll
            for (int ky = 0; ky < 3; ky++) {
                const int rbase = ((py + ky) * 18 + px0) * 33 + ch;
                float cv[6];
#pragma unroll
                for (int j = 0; j < 6; j++) cv[j] = sA[rbase + j * 33];
                const float w0 = sW[(ky * 3 + 0) * SC + c0 + ch];
                const float w1 = sW[(ky * 3 + 1) * SC + c0 + ch];
                const float w2 = sW[(ky * 3 + 2) * SC + c0 + ch];
                a0 += w0 * cv[0] + w1 * cv[1] + w2 * cv[2];
                a1 += w0 * cv[1] + w1 * cv[2] + w2 * cv[3];
                a2 += w0 * cv[2] + w1 * cv[3] + w2 * cv[4];
                a3 += w0 * cv[3] + w1 * cv[4] + w2 * cv[5];
            }
            const float bs = dwb[g * SC + c0 + ch];
            *(float4*)&dsh[ch * 260 + p4 * 4] =
                make_float4(a0 + bs, a1 + bs, a2 + bs, a3 + bs);
        }
        __syncthreads();

        // ----- phase 2: pointwise GEMM over this 32-channel chunk -----
#pragma unroll 4
        for (int chl = 0; chl < 32; chl++) {
            const ulonglong2* dp = (const ulonglong2*)&dsh[chl * 260 + lane * 8];
            const ulonglong2 dA = dp[0];
            const ulonglong2 dB = dp[1];
            const float4* wv = (const float4*)(sP + chl * 64 + fg * 8);
            const float4 wlo = wv[0];
            const float4 whi = wv[1];
            const float wf[8] = {wlo.x, wlo.y, wlo.z, wlo.w,
                                 whi.x, whi.y, whi.z, whi.w};
#pragma unroll
            for (int f = 0; f < 8; f++) {
                const unsigned long long wp2 = pack2(wf[f], wf[f]);
                acc[f][0] = fma2(dA.x, wp2, acc[f][0]);
                acc[f][1] = fma2(dA.y, wp2, acc[f][1]);
                acc[f][2] = fma2(dB.x, wp2, acc[f][2]);
                acc[f][3] = fma2(dB.y, wp2, acc[f][3]);
            }
        }
    }

    // ----- epilogue: bias + store -----
    float bias[8];
#pragma unroll
    for (int f = 0; f < 8; f++) bias[f] = pwb[g * 64 + fg * 8 + f];

#pragma unroll
    for (int pp = 0; pp < 4; pp++) {
        float2 u[8];
#pragma unroll
        for (int f = 0; f < 8; f++) u[f] = unpack2(acc[f][pp]);
#pragma unroll
        for (int half = 0; half < 2; half++) {
            const int lpix = lane * 8 + pp * 2 + half;
            const int py = lpix >> 4, px = lpix & 15;
            float* op = out + ((size_t)b * HW + (ty0 + py) * Ww + (tx0 + px)) * 128
                        + g * 64 + fg * 8;
            float v[8];
#pragma unroll
            for (int f = 0; f < 8; f++)
                v[f] = (half ? u[f].y : u[f].x) + bias[f];
            ((float4*)op)[0] = make_float4(v[0], v[1], v[2], v[3]);
            ((float4*)op)[1] = make_float4(v[4], v[5], v[6], v[7]);
        }
    }
}

// =====================================================================
// launch
// =====================================================================
extern "C" void kernel_launch(void* const* d_in, const int* in_sizes, int n_in,
                              void* d_out, int out_size)
{
    const float* x    = (const float*)d_in[0];
    const float* ow   = (const float*)d_in[1];
    const float* obia = (const float*)d_in[2];
    const float* dww  = (const float*)d_in[3];
    const float* dwbi = (const float*)d_in[4];
    const float* pww  = (const float*)d_in[5];
    const float* pwbi = (const float*)d_in[6];
    float* out = (float*)d_out;

    const int smemA = (34 * 18 * 33 + 9 * 32 * 18) * 4;          // 101520 B
    const int smemC = (10692 + 8320 + 2592 + 2048) * 4;          //  94608 B
    cudaFuncSetAttribute(k_offconv, cudaFuncAttributeMaxDynamicSharedMemorySize, smemA);
    cudaFuncSetAttribute(k_dwpw,    cudaFuncAttributeMaxDynamicSharedMemorySize, smemC);

    k_offconv<<<dim3(8, 4, Bb * Gg), 256, smemA>>>(x, ow, obia);
    k_sample<<<(Bb * Gg * HW * 9 * 8) / 256, 256>>>(x);
    k_dwpw<<<dim3(8, 8, Bb * Gg), 256, smemC>>>(dww, dwbi, pww, pwbi, out);
}

// round 13
// speedup vs baseline: 1.2820x; 1.2820x over previous
#include <cuda_runtime.h>
#include <cstdint>

#define Hh 128
#define Ww 128
#define HW (128*128)
#define Bb 8
#define Gg 2
#define GC 32
#define SC 288
#define GF 64

// ---------------- scratch (allocation-free: __device__ global) ----------------
__device__ float g_off[(size_t)Bb*Gg*HW*18];          // offsets, [bg][p][k][2]

// ---------------- f32x2 packed helpers ----------------
__device__ __forceinline__ unsigned long long pack2(float a, float b) {
    unsigned long long d;
    asm("mov.b64 %0, {%1, %2};" : "=l"(d) : "f"(a), "f"(b));
    return d;
}
__device__ __forceinline__ float2 unpack2(unsigned long long v) {
    float2 r;
    asm("mov.b64 {%0, %1}, %2;" : "=f"(r.x), "=f"(r.y) : "l"(v));
    return r;
}
__device__ __forceinline__ unsigned long long fma2(unsigned long long a,
                                                   unsigned long long b,
                                                   unsigned long long c) {
    unsigned long long d;
    asm("fma.rn.f32x2 %0, %1, %2, %3;" : "=l"(d) : "l"(a), "l"(b), "l"(c));
    return d;
}

// =====================================================================
// Kernel A: offset conv (3x3, 32 -> 18 ch, SAME, per group)
// grid (8, 8, B*G): 16x16 tile, 256 threads, 1 pixel/thread.
// smem 63.5KB -> 3 blocks/SM.
// =====================================================================
__global__ void __launch_bounds__(256, 3) k_offconv(const float* __restrict__ x,
                                                    const float* __restrict__ ow,
                                                    const float* __restrict__ ob)
{
    extern __shared__ float s[];
    float* s_in = s;                         // 18*18*33 = 10692 (scalar access only)
    float* s_w  = s + 10692;                 // 9*32*18  = 5184

    const int bg = blockIdx.z;
    const int b = bg >> 1, g = bg & 1;
    const int tx0 = blockIdx.x * 16, ty0 = blockIdx.y * 16;
    const float* xb = x + (size_t)b * HW * 64 + g * 32;
    const float* wg = ow + (size_t)g * 9 * 32 * 18;

    for (int i = threadIdx.x; i < 9 * 32 * 18; i += 256) s_w[i] = wg[i];

    for (int i = threadIdx.x; i < 324 * 32; i += 256) {
        int c   = i & 31;
        int pos = i >> 5;
        int col = pos % 18, row = pos / 18;
        int gy = ty0 - 1 + row, gx = tx0 - 1 + col;
        float v = 0.f;
        if ((unsigned)gy < Hh && (unsigned)gx < Ww)
            v = xb[(size_t)(gy * Ww + gx) * 64 + c];
        s_in[pos * 33 + c] = v;
    }
    __syncthreads();

    const int tx = threadIdx.x & 15, ty = threadIdx.x >> 4;

    unsigned long long acc[9];
    const float2* ob2 = (const float2*)(ob + g * 18);
#pragma unroll
    for (int j = 0; j < 9; j++) {
        float2 bb = ob2[j];
        acc[j] = pack2(bb.x, bb.y);
    }

#pragma unroll
    for (int ky = 0; ky < 3; ky++) {
#pragma unroll
        for (int kx = 0; kx < 3; kx++) {
            const float* wt = s_w + (size_t)((ky * 3 + kx) * 32) * 18;
            const int sb0 = ((ty + ky) * 18 + tx + kx) * 33;
#pragma unroll 8
            for (int c = 0; c < 32; c++) {
                float v0 = s_in[sb0 + c];
                unsigned long long p0 = pack2(v0, v0);
                const unsigned long long* wp =
                    (const unsigned long long*)(wt + c * 18);
#pragma unroll
                for (int j = 0; j < 9; j++)
                    acc[j] = fma2(p0, wp[j], acc[j]);
            }
        }
    }

    unsigned long long* o0 = (unsigned long long*)(g_off +
        ((size_t)bg * HW + (ty0 + ty) * Ww + (tx0 + tx)) * 18);
#pragma unroll
    for (int j = 0; j < 9; j++) o0[j] = acc[j];
}

// =====================================================================
// Kernel C (fused): bilinear sampling + depthwise 3x3 + pointwise (SC->64).
// grid (8, 8, B*G): 16x16 pixel tile, 256 threads.
// sA row stride = 36 floats (multiple of 4 -> STS.128 aligned; the 33-stride
// float4 write was the R4/R5 misaligned-address trap).
// =====================================================================
__global__ void __launch_bounds__(256, 2) k_fused(const float* __restrict__ x,
                                                  const float* __restrict__ dww,
                                                  const float* __restrict__ dwb,
                                                  const float* __restrict__ pww,
                                                  const float* __restrict__ pwb,
                                                  float* __restrict__ out)
{
    extern __shared__ float sm[];
    float* sA  = sm;                          // 324*36  = 11664 (halo samples)
    float* dsh = sm + 11664;                  // 32*260  = 8320  (dw out, [ch][pix])
    float* sW  = sm + 11664 + 8320;           // 9*288   = 2592  (dw weights)
    float* sP  = sm + 11664 + 8320 + 2592;    // 32*64   = 2048  (pw weight slab)

    const int bg = blockIdx.z;
    const int b = bg >> 1, g = bg & 1;
    const int tx0 = blockIdx.x * 16, ty0 = blockIdx.y * 16;
    const int tid = threadIdx.x;
    const int lane = tid & 31, fg = tid >> 5;
    const float* xg = x + (size_t)b * HW * 64 + g * 32;
    const float2* offb = (const float2*)g_off + (size_t)bg * HW * 9;

    // stage depthwise weights once: sW[(ky*3+kx)*288 + ch]
    for (int i = tid; i < 9 * SC; i += 256) sW[i] = dww[(size_t)g * 9 * SC + i];

    unsigned long long acc[8][4];
#pragma unroll
    for (int f = 0; f < 8; f++)
#pragma unroll
        for (int q = 0; q < 4; q++) acc[f][q] = 0ull;

    const float dxk[3] = {-1.f, 0.f, 1.f};

    for (int k = 0; k < 9; k++) {
        const int c0 = k * 32;
        const float dx = dxk[k % 3], dy = dxk[k / 3];
        __syncthreads();   // prev GEMM done reading dsh/sP before restage

        // ----- stage A: sample halo tile (18x18 pixels x 32ch) from x -----
        for (int i = tid; i < 324 * 8; i += 256) {
            const int c4  = i & 7;
            const int pos = i >> 3;
            const int col = pos % 18, row = pos / 18;
            const int gy = ty0 - 1 + row, gx = tx0 - 1 + col;
            float4 r = make_float4(0.f, 0.f, 0.f, 0.f);
            if ((unsigned)gy < Hh && (unsigned)gx < Ww) {
                const float2 off2 = offb[(size_t)(gy * Ww + gx) * 9 + k];
                float lx = (float)gx + dx + off2.x;
                float ly = (float)gy + dy + off2.y;
                lx = fminf(fmaxf(lx, 0.f), 127.f);
                ly = fminf(fmaxf(ly, 0.f), 127.f);
                float fx = floorf(lx), fy = floorf(ly);
                float x0f = fminf(fmaxf(fx, 0.f), 127.f);
                float x1f = fminf(fmaxf(fx + 1.f, 0.f), 127.f);
                float y0f = fminf(fmaxf(fy, 0.f), 127.f);
                float y1f = fminf(fmaxf(fy + 1.f, 0.f), 127.f);
                float wa = (x1f - lx) * (y1f - ly);
                float wb = (x1f - lx) * (ly - y0f);
                float wc = (lx - x0f) * (y1f - ly);
                float wd = (lx - x0f) * (ly - y0f);
                int x0 = (int)x0f, x1 = (int)x1f, y0 = (int)y0f, y1 = (int)y1f;
                const float* xc = xg + c4 * 4;
                const float4 Ia = *(const float4*)(xc + (size_t)(y0 * Ww + x0) * 64);
                const float4 Ib = *(const float4*)(xc + (size_t)(y1 * Ww + x0) * 64);
                const float4 Ic = *(const float4*)(xc + (size_t)(y0 * Ww + x1) * 64);
                const float4 Id = *(const float4*)(xc + (size_t)(y1 * Ww + x1) * 64);
                r.x = wa * Ia.x + wb * Ib.x + wc * Ic.x + wd * Id.x;
                r.y = wa * Ia.y + wb * Ib.y + wc * Ic.y + wd * Id.y;
                r.z = wa * Ia.z + wb * Ib.z + wc * Ic.z + wd * Id.z;
                r.w = wa * Ia.w + wb * Ib.w + wc * Ic.w + wd * Id.w;
            }
            *(float4*)&sA[pos * 36 + c4 * 4] = r;   // 36-stride: 16B aligned
        }
        // ----- stage B: pw weight slab -----
        for (int i = tid; i < 32 * 64; i += 256)
            sP[i] = pww[((size_t)g * SC + c0) * 64 + i];
        __syncthreads();

        // ----- phase 1: depthwise into dsh, transposed [ch][pix] -----
        for (int it = tid; it < 64 * 32; it += 256) {
            const int ch = it & 31;          // warp = 32 consecutive ch
            const int p4 = it >> 5;          // 4 consecutive pixels
            const int px0 = (p4 & 3) * 4;
            const int py  = p4 >> 2;
            float a0 = 0.f, a1 = 0.f, a2 = 0.f, a3 = 0.f;
#pragma unroll
            for (int ky = 0; ky < 3; ky++) {
                const int rbase = ((py + ky) * 18 + px0) * 36 + ch;
                float cv[6];
#pragma unroll
                for (int j = 0; j < 6; j++) cv[j] = sA[rbase + j * 36];
                const float w0 = sW[(ky * 3 + 0) * SC + c0 + ch];
                const float w1 = sW[(ky * 3 + 1) * SC + c0 + ch];
                const float w2 = sW[(ky * 3 + 2) * SC + c0 + ch];
                a0 += w0 * cv[0] + w1 * cv[1] + w2 * cv[2];
                a1 += w0 * cv[1] + w1 * cv[2] + w2 * cv[3];
                a2 += w0 * cv[2] + w1 * cv[3] + w2 * cv[4];
                a3 += w0 * cv[3] + w1 * cv[4] + w2 * cv[5];
            }
            const float bs = dwb[g * SC + c0 + ch];
            *(float4*)&dsh[ch * 260 + p4 * 4] =
                make_float4(a0 + bs, a1 + bs, a2 + bs, a3 + bs);
        }
        __syncthreads();

        // ----- phase 2: pointwise GEMM over this 32-channel chunk -----
#pragma unroll 4
        for (int chl = 0; chl < 32; chl++) {
            const ulonglong2* dp = (const ulonglong2*)&dsh[chl * 260 + lane * 8];
            const ulonglong2 dA = dp[0];
            const ulonglong2 dB = dp[1];
            const float4* wv = (const float4*)(sP + chl * 64 + fg * 8);
            const float4 wlo = wv[0];
            const float4 whi = wv[1];
            const float wf[8] = {wlo.x, wlo.y, wlo.z, wlo.w,
                                 whi.x, whi.y, whi.z, whi.w};
#pragma unroll
            for (int f = 0; f < 8; f++) {
                const unsigned long long wp2 = pack2(wf[f], wf[f]);
                acc[f][0] = fma2(dA.x, wp2, acc[f][0]);
                acc[f][1] = fma2(dA.y, wp2, acc[f][1]);
                acc[f][2] = fma2(dB.x, wp2, acc[f][2]);
                acc[f][3] = fma2(dB.y, wp2, acc[f][3]);
            }
        }
    }

    // ----- epilogue: bias + store -----
    float bias[8];
#pragma unroll
    for (int f = 0; f < 8; f++) bias[f] = pwb[g * 64 + fg * 8 + f];

#pragma unroll
    for (int pp = 0; pp < 4; pp++) {
        float2 u[8];
#pragma unroll
        for (int f = 0; f < 8; f++) u[f] = unpack2(acc[f][pp]);
#pragma unroll
        for (int half = 0; half < 2; half++) {
            const int lpix = lane * 8 + pp * 2 + half;
            const int py = lpix >> 4, px = lpix & 15;
            float* op = out + ((size_t)b * HW + (ty0 + py) * Ww + (tx0 + px)) * 128
                        + g * 64 + fg * 8;
            float v[8];
#pragma unroll
            for (int f = 0; f < 8; f++)
                v[f] = (half ? u[f].y : u[f].x) + bias[f];
            ((float4*)op)[0] = make_float4(v[0], v[1], v[2], v[3]);
            ((float4*)op)[1] = make_float4(v[4], v[5], v[6], v[7]);
        }
    }
}

// =====================================================================
// launch
// =====================================================================
extern "C" void kernel_launch(void* const* d_in, const int* in_sizes, int n_in,
                              void* d_out, int out_size)
{
    const float* x    = (const float*)d_in[0];
    const float* ow   = (const float*)d_in[1];
    const float* obia = (const float*)d_in[2];
    const float* dww  = (const float*)d_in[3];
    const float* dwbi = (const float*)d_in[4];
    const float* pww  = (const float*)d_in[5];
    const float* pwbi = (const float*)d_in[6];
    float* out = (float*)d_out;

    const int smemA = (10692 + 5184) * 4;                        // 63504 B
    const int smemC = (11664 + 8320 + 2592 + 2048) * 4;          // 98496 B
    cudaFuncSetAttribute(k_offconv, cudaFuncAttributeMaxDynamicSharedMemorySize, smemA);
    cudaFuncSetAttribute(k_fused,   cudaFuncAttributeMaxDynamicSharedMemorySize, smemC);

    k_offconv<<<dim3(8, 8, Bb * Gg), 256, smemA>>>(x, ow, obia);
    k_fused<<<dim3(8, 8, Bb * Gg), 256, smemC>>>(x, dww, dwbi, pww, pwbi, out);
}